// round 1
// baseline (speedup 1.0000x reference)
#include <cuda_runtime.h>
#include <cuda_bf16.h>
#include <cstdint>

#define NNODES 100000
#define NEDGES 1600000
#define DFEAT  64
#define NBLK   98          // ceil(NNODES/1024)

// ---------------- device scratch (static, no allocation) ----------------
__device__ int   g_deg_out[NNODES];
__device__ int   g_deg_in[NNODES];
__device__ float g_o[NNODES];          // out_deg^{-1/2} (0 if deg==0)
__device__ float g_i[NNODES];          // in_deg^{-1/2}
__device__ int   g_rowptrA[NNODES + 1];
__device__ int   g_rowptrAT[NNODES + 1];
__device__ int   g_curA[NNODES];
__device__ int   g_curAT[NNODES];
__device__ int   g_colA[NEDGES];
__device__ int   g_colAT[NEDGES];
__device__ int   g_scan1[NNODES];
__device__ int   g_scan2[NNODES];
__device__ int   g_bsums1[128];
__device__ int   g_bsums2[128];
__device__ float g_y1[(size_t)NNODES * DFEAT];
__device__ float g_y2[(size_t)NNODES * DFEAT];
__device__ float g_Z [(size_t)NNODES * DFEAT];
__device__ float g_bias[DFEAT];
__device__ float g_W0sum[DFEAT * DFEAT];

// ---------------- preprocessing kernels ----------------
__global__ void zero_deg_kernel() {
    int i = blockIdx.x * blockDim.x + threadIdx.x;
    if (i < NNODES) { g_deg_out[i] = 0; g_deg_in[i] = 0; }
}

__global__ void count_deg_kernel(const int* __restrict__ ei) {
    int e = blockIdx.x * blockDim.x + threadIdx.x;
    if (e < NEDGES) {
        atomicAdd(&g_deg_out[ei[e]], 1);
        atomicAdd(&g_deg_in[ei[NEDGES + e]], 1);
    }
}

__global__ void norm_kernel() {
    int i = blockIdx.x * blockDim.x + threadIdx.x;
    if (i < NNODES) {
        int dout = g_deg_out[i];
        int din  = g_deg_in[i];
        g_o[i] = (dout > 0) ? (1.0f / sqrtf((float)dout)) : 0.0f;
        g_i[i] = (din  > 0) ? (1.0f / sqrtf((float)din))  : 0.0f;
    }
}

// sel==0 -> scan deg_out into scan1/bsums1 ; sel==1 -> deg_in into scan2/bsums2
__global__ void scan_partial_kernel(int sel) {
    __shared__ int s[1024];
    const int* deg = sel ? g_deg_in : g_deg_out;
    int* scanbuf   = sel ? g_scan2  : g_scan1;
    int* bsums     = sel ? g_bsums2 : g_bsums1;
    int i = blockIdx.x * 1024 + threadIdx.x;
    int v = (i < NNODES) ? deg[i] : 0;
    s[threadIdx.x] = v;
    __syncthreads();
    for (int off = 1; off < 1024; off <<= 1) {
        int t = (threadIdx.x >= off) ? s[threadIdx.x - off] : 0;
        __syncthreads();
        s[threadIdx.x] += t;
        __syncthreads();
    }
    if (i < NNODES) scanbuf[i] = s[threadIdx.x];
    if (threadIdx.x == 1023) bsums[blockIdx.x] = s[1023];
}

__global__ void scan_sums_kernel(int sel) {
    __shared__ int s[128];
    int* bsums = sel ? g_bsums2 : g_bsums1;
    int v = (threadIdx.x < NBLK) ? bsums[threadIdx.x] : 0;
    s[threadIdx.x] = v;
    __syncthreads();
    for (int off = 1; off < 128; off <<= 1) {
        int t = (threadIdx.x >= off) ? s[threadIdx.x - off] : 0;
        __syncthreads();
        s[threadIdx.x] += t;
        __syncthreads();
    }
    if (threadIdx.x < NBLK) bsums[threadIdx.x] = s[threadIdx.x] - v;  // exclusive
}

__global__ void scan_final_kernel(int sel) {
    const int* deg     = sel ? g_deg_in : g_deg_out;
    const int* scanbuf = sel ? g_scan2  : g_scan1;
    const int* bsums   = sel ? g_bsums2 : g_bsums1;
    int* rowptr        = sel ? g_rowptrAT : g_rowptrA;
    int* cursor        = sel ? g_curAT    : g_curA;
    int i = blockIdx.x * blockDim.x + threadIdx.x;
    if (i < NNODES) {
        int excl = scanbuf[i] + bsums[i >> 10] - deg[i];
        rowptr[i] = excl;
        cursor[i] = excl;
    }
    if (i == 0) rowptr[NNODES] = NEDGES;
}

__global__ void fill_csr_kernel(const int* __restrict__ ei) {
    int e = blockIdx.x * blockDim.x + threadIdx.x;
    if (e < NEDGES) {
        int r = ei[e];
        int c = ei[NEDGES + e];
        int p = atomicAdd(&g_curA[r], 1);
        g_colA[p] = c;
        int q = atomicAdd(&g_curAT[c], 1);
        g_colAT[q] = r;
    }
}

__global__ void prep_wb_kernel(const float* __restrict__ bssd, const float* __restrict__ bsds,
                               const float* __restrict__ b0sd, const float* __restrict__ b0ds,
                               const float* __restrict__ w0sd, const float* __restrict__ w0ds) {
    int t = blockIdx.x * blockDim.x + threadIdx.x;
    if (t < DFEAT * DFEAT) g_W0sum[t] = w0sd[t] + w0ds[t];
    if (t < DFEAT) {
        float b = b0sd[t] + b0ds[t];
        float sc = 1.0f;
        #pragma unroll
        for (int k = 0; k < 4; k++) {
            b += sc * (bssd[k * DFEAT + t] + bsds[k * DFEAT + t]);
            sc *= 0.5f;
        }
        g_bias[t] = 0.5f * b;
    }
}

// ---------------- SpMM: out[r,:] (=/+=) sself[r] * sum_k snbr[idx] * h[idx,:] ----------------
// 16 lanes per row, 4 features (float4) per lane.
__global__ void spmm_kernel(int sel, const float* __restrict__ h, float* __restrict__ out, int acc) {
    const int* rowptr = sel ? g_rowptrAT : g_rowptrA;
    const int* cidx   = sel ? g_colAT    : g_colA;
    const float* ss   = sel ? g_i : g_o;
    const float* sn   = sel ? g_o : g_i;

    int gt = blockIdx.x * blockDim.x + threadIdx.x;
    int r = gt >> 4;
    if (r >= NNODES) return;
    int lane = (gt & 15) << 2;

    int beg = rowptr[r];
    int end = rowptr[r + 1];
    float a0 = 0.f, a1 = 0.f, a2 = 0.f, a3 = 0.f;

    int k = beg;
    if (k < end) {
        int c = __ldg(cidx + k);
        for (;;) {
            int kn = k + 1;
            int cn = (kn < end) ? __ldg(cidx + kn) : 0;
            float v = __ldg(sn + c);
            const float4 hv = *reinterpret_cast<const float4*>(h + ((size_t)c << 6) + lane);
            a0 = fmaf(v, hv.x, a0);
            a1 = fmaf(v, hv.y, a1);
            a2 = fmaf(v, hv.z, a2);
            a3 = fmaf(v, hv.w, a3);
            if (kn >= end) break;
            k = kn; c = cn;
        }
    }
    float s = ss[r];
    size_t o = ((size_t)r << 6) + lane;
    float4 res;
    if (acc) {
        float4 p = *reinterpret_cast<float4*>(out + o);
        res.x = fmaf(s, a0, p.x);
        res.y = fmaf(s, a1, p.y);
        res.z = fmaf(s, a2, p.z);
        res.w = fmaf(s, a3, p.w);
    } else {
        res.x = s * a0; res.y = s * a1; res.z = s * a2; res.w = s * a3;
    }
    *reinterpret_cast<float4*>(out + o) = res;
}

// ---------------- GEMM: OA (+)= cA * Y @ Wa^T  [, OB (+)= cB * Y @ Wb^T] ----------------
// Tile: 64 rows x 64 cols per block, 128 threads, 4x8 register tile per thread.
__device__ __forceinline__ void stage_transposed(float* dst, const float* __restrict__ src64x64,
                                                 int lrow, int dp0, bool ok) {
    const float4* src = reinterpret_cast<const float4*>(src64x64 + (size_t)lrow * 64);
    #pragma unroll
    for (int dp = dp0; dp < 16; dp += 2) {
        float4 v = ok ? __ldg(src + dp) : make_float4(0.f, 0.f, 0.f, 0.f);
        int d = dp << 2;
        dst[(d + 0) * 64 + lrow] = v.x;
        dst[(d + 1) * 64 + lrow] = v.y;
        dst[(d + 2) * 64 + lrow] = v.z;
        dst[(d + 3) * 64 + lrow] = v.w;
    }
}

__global__ __launch_bounds__(128) void gemm_dual_kernel(
    const float* __restrict__ Y,
    const float* __restrict__ Wa, float* __restrict__ OA, float cA, int accA, int addBias,
    const float* __restrict__ Wb, float* __restrict__ OB, float cB, int accB, int useB)
{
    __shared__ float syT[64 * 64];
    __shared__ float swT[64 * 64];
    const int tid  = threadIdx.x;
    const int row0 = blockIdx.x * 64;
    const int lrow = tid & 63;
    const int dp0  = tid >> 6;

    // stage Y^T (rows of this block's tile)
    {
        bool ok = (row0 + lrow) < NNODES;
        const float4* src = reinterpret_cast<const float4*>(Y + (size_t)(row0 + lrow) * 64);
        #pragma unroll
        for (int dp = dp0; dp < 16; dp += 2) {
            float4 v = ok ? __ldg(src + dp) : make_float4(0.f, 0.f, 0.f, 0.f);
            int d = dp << 2;
            syT[(d + 0) * 64 + lrow] = v.x;
            syT[(d + 1) * 64 + lrow] = v.y;
            syT[(d + 2) * 64 + lrow] = v.z;
            syT[(d + 3) * 64 + lrow] = v.w;
        }
    }
    stage_transposed(swT, Wa, lrow, dp0, true);
    __syncthreads();

    const int r0 = ((tid >> 3) & 15) << 2;
    const int c0 = (tid & 7) << 3;

    float acc[4][8];
    #pragma unroll
    for (int i = 0; i < 4; i++)
        #pragma unroll
        for (int j = 0; j < 8; j++) acc[i][j] = 0.f;

    #pragma unroll 8
    for (int d = 0; d < 64; d++) {
        const float4 yv = *reinterpret_cast<const float4*>(&syT[d * 64 + r0]);
        const float4 wl = *reinterpret_cast<const float4*>(&swT[d * 64 + c0]);
        const float4 wh = *reinterpret_cast<const float4*>(&swT[d * 64 + c0 + 4]);
        float yr[4] = {yv.x, yv.y, yv.z, yv.w};
        float wc[8] = {wl.x, wl.y, wl.z, wl.w, wh.x, wh.y, wh.z, wh.w};
        #pragma unroll
        for (int i = 0; i < 4; i++)
            #pragma unroll
            for (int j = 0; j < 8; j++)
                acc[i][j] = fmaf(yr[i], wc[j], acc[i][j]);
    }

    // write phase A
    #pragma unroll
    for (int i = 0; i < 4; i++) {
        int r = row0 + r0 + i;
        if (r < NNODES) {
            float* dst = OA + ((size_t)r << 6) + c0;
            float v[8];
            #pragma unroll
            for (int j = 0; j < 8; j++) v[j] = cA * acc[i][j];
            if (addBias) {
                #pragma unroll
                for (int j = 0; j < 8; j++) v[j] += g_bias[c0 + j];
            }
            if (accA) {
                float4 p0 = *reinterpret_cast<float4*>(dst);
                float4 p1 = *reinterpret_cast<float4*>(dst + 4);
                v[0] += p0.x; v[1] += p0.y; v[2] += p0.z; v[3] += p0.w;
                v[4] += p1.x; v[5] += p1.y; v[6] += p1.z; v[7] += p1.w;
            }
            *reinterpret_cast<float4*>(dst)     = make_float4(v[0], v[1], v[2], v[3]);
            *reinterpret_cast<float4*>(dst + 4) = make_float4(v[4], v[5], v[6], v[7]);
        }
    }

    if (useB) {
        __syncthreads();
        stage_transposed(swT, Wb, lrow, dp0, true);
        __syncthreads();

        #pragma unroll
        for (int i = 0; i < 4; i++)
            #pragma unroll
            for (int j = 0; j < 8; j++) acc[i][j] = 0.f;

        #pragma unroll 8
        for (int d = 0; d < 64; d++) {
            const float4 yv = *reinterpret_cast<const float4*>(&syT[d * 64 + r0]);
            const float4 wl = *reinterpret_cast<const float4*>(&swT[d * 64 + c0]);
            const float4 wh = *reinterpret_cast<const float4*>(&swT[d * 64 + c0 + 4]);
            float yr[4] = {yv.x, yv.y, yv.z, yv.w};
            float wc[8] = {wl.x, wl.y, wl.z, wl.w, wh.x, wh.y, wh.z, wh.w};
            #pragma unroll
            for (int i = 0; i < 4; i++)
                #pragma unroll
                for (int j = 0; j < 8; j++)
                    acc[i][j] = fmaf(yr[i], wc[j], acc[i][j]);
        }

        #pragma unroll
        for (int i = 0; i < 4; i++) {
            int r = row0 + r0 + i;
            if (r < NNODES) {
                float* dst = OB + ((size_t)r << 6) + c0;
                float v[8];
                #pragma unroll
                for (int j = 0; j < 8; j++) v[j] = cB * acc[i][j];
                if (accB) {
                    float4 p0 = *reinterpret_cast<float4*>(dst);
                    float4 p1 = *reinterpret_cast<float4*>(dst + 4);
                    v[0] += p0.x; v[1] += p0.y; v[2] += p0.z; v[3] += p0.w;
                    v[4] += p1.x; v[5] += p1.y; v[6] += p1.z; v[7] += p1.w;
                }
                *reinterpret_cast<float4*>(dst)     = make_float4(v[0], v[1], v[2], v[3]);
                *reinterpret_cast<float4*>(dst + 4) = make_float4(v[4], v[5], v[6], v[7]);
            }
        }
    }
}

// ---------------- launch ----------------
extern "C" void kernel_launch(void* const* d_in, const int* in_sizes, int n_in,
                              void* d_out, int out_size) {
    const float* x    = (const float*)d_in[0];
    const int*   ei   = (const int*)d_in[1];
    const float* Wsd  = (const float*)d_in[2];
    const float* bssd = (const float*)d_in[3];
    const float* Wds  = (const float*)d_in[4];
    const float* bsds = (const float*)d_in[5];
    const float* W0sd = (const float*)d_in[6];
    const float* b0sd = (const float*)d_in[7];
    const float* W0ds = (const float*)d_in[8];
    const float* b0ds = (const float*)d_in[9];
    float* out = (float*)d_out;

    void* tmp;
    cudaGetSymbolAddress(&tmp, g_y1);    float* y1 = (float*)tmp;
    cudaGetSymbolAddress(&tmp, g_y2);    float* y2 = (float*)tmp;
    cudaGetSymbolAddress(&tmp, g_Z);     float* Z  = (float*)tmp;
    cudaGetSymbolAddress(&tmp, g_W0sum); float* W0sum = (float*)tmp;

    const int nblk_nodes = (NNODES + 255) / 256;            // 391
    const int nblk_edges = (NEDGES + 255) / 256;            // 6250
    const int nblk_spmm  = (NNODES * 16 + 255) / 256;       // 6250
    const int nblk_gemm  = (NNODES + 63) / 64;              // 1563

    // ---- preprocessing ----
    zero_deg_kernel<<<nblk_nodes, 256>>>();
    count_deg_kernel<<<nblk_edges, 256>>>(ei);
    norm_kernel<<<nblk_nodes, 256>>>();
    scan_partial_kernel<<<NBLK, 1024>>>(0);
    scan_partial_kernel<<<NBLK, 1024>>>(1);
    scan_sums_kernel<<<1, 128>>>(0);
    scan_sums_kernel<<<1, 128>>>(1);
    scan_final_kernel<<<nblk_nodes, 256>>>(0);
    scan_final_kernel<<<nblk_nodes, 256>>>(1);
    fill_csr_kernel<<<nblk_edges, 256>>>(ei);
    prep_wb_kernel<<<16, 256>>>(bssd, bsds, b0sd, b0ds, W0sd, W0ds);

    // ---- main pipeline ----
    // y1 = A x
    spmm_kernel<<<nblk_spmm, 256>>>(0, x, y1, 0);
    // out = bias + 0.5 x (W0sd+W0ds)^T ; Z = 0.5 x Wds0^T
    gemm_dual_kernel<<<nblk_gemm, 128>>>(x, W0sum, out, 0.5f, 0, 1,
                                         Wds, Z, 0.5f, 0, 1);
    // out += 0.5 y1 Wsd0^T
    gemm_dual_kernel<<<nblk_gemm, 128>>>(y1, Wsd, out, 0.5f, 1, 0,
                                         nullptr, nullptr, 0.f, 0, 0);
    // y2 = A y1
    spmm_kernel<<<nblk_spmm, 256>>>(0, y1, y2, 0);
    // out += 0.25 y2 Wsd1^T ; Z += 0.25 y2 Wds1^T
    gemm_dual_kernel<<<nblk_gemm, 128>>>(y2, Wsd + 4096, out, 0.25f, 1, 0,
                                         Wds + 4096, Z, 0.25f, 1, 1);
    // y3 = A y2  (into y1 buffer)
    spmm_kernel<<<nblk_spmm, 256>>>(0, y2, y1, 0);
    gemm_dual_kernel<<<nblk_gemm, 128>>>(y1, Wsd + 8192, out, 0.125f, 1, 0,
                                         Wds + 8192, Z, 0.125f, 1, 1);
    // y4 = A y3  (into y2 buffer)
    spmm_kernel<<<nblk_spmm, 256>>>(0, y1, y2, 0);
    gemm_dual_kernel<<<nblk_gemm, 128>>>(y2, Wsd + 12288, out, 0.0625f, 1, 0,
                                         Wds + 12288, Z, 0.0625f, 1, 1);
    // out += A^T Z   (collapses all 4 transposed-direction SpMMs into one)
    spmm_kernel<<<nblk_spmm, 256>>>(1, Z, out, 1);
}

// round 2
// speedup vs baseline: 1.3274x; 1.3274x over previous
#include <cuda_runtime.h>
#include <cstdint>

#define NNODES 100000
#define NEDGES 1600000
#define NBLK   98          // ceil(NNODES/1024)

// ---------------- device scratch ----------------
__device__ int   g_deg_out[NNODES];
__device__ int   g_deg_in[NNODES];
__device__ float g_o[NNODES];
__device__ float g_i[NNODES];
__device__ int   g_rowptrA[NNODES + 1];
__device__ int   g_rowptrAT[NNODES + 1];
__device__ int   g_curA[NNODES];
__device__ int   g_curAT[NNODES];
__device__ int2  g_eA[NEDGES];     // {col, float_bits(val)}
__device__ int2  g_eAT[NEDGES];
__device__ int   g_scan[2 * NNODES];
__device__ int   g_bsums[256];
__device__ float g_y1[(size_t)NNODES * 64];
__device__ float g_y2[(size_t)NNODES * 64];
__device__ float g_y3[(size_t)NNODES * 64];
__device__ float g_y4[(size_t)NNODES * 64];
__device__ float g_Z [(size_t)NNODES * 64];
__device__ float g_bias[64];
__device__ float g_U[128 * 320];   // fused weight matrix (coeffs folded)

// ---------------- f32x2 helpers ----------------
__device__ __forceinline__ unsigned long long dup2(float a) {
    unsigned long long r;
    asm("mov.b64 %0, {%1, %1};" : "=l"(r) : "f"(a));
    return r;
}
__device__ __forceinline__ void ffma2(unsigned long long& d, unsigned long long a, unsigned long long b) {
    asm("fma.rn.f32x2 %0, %1, %2, %0;" : "+l"(d) : "l"(a), "l"(b));
}
__device__ __forceinline__ float2 unpk(unsigned long long v) {
    float2 f;
    asm("mov.b64 {%0, %1}, %2;" : "=f"(f.x), "=f"(f.y) : "l"(v));
    return f;
}

// ---------------- preprocessing ----------------
__global__ void zero_deg_kernel() {
    int i = blockIdx.x * blockDim.x + threadIdx.x;
    if (i < NNODES) { g_deg_out[i] = 0; g_deg_in[i] = 0; }
}

__global__ void count_deg_kernel(const int* __restrict__ ei) {
    int e = blockIdx.x * blockDim.x + threadIdx.x;
    if (e < NEDGES) {
        atomicAdd(&g_deg_out[ei[e]], 1);
        atomicAdd(&g_deg_in[ei[NEDGES + e]], 1);
    }
}

__global__ void scan_partial_kernel() {
    __shared__ int s[1024];
    int sel = blockIdx.y;
    const int* deg = sel ? g_deg_in : g_deg_out;
    int* scanbuf = g_scan + sel * NNODES;
    int* bsums   = g_bsums + sel * 128;
    int i = blockIdx.x * 1024 + threadIdx.x;
    int v = (i < NNODES) ? deg[i] : 0;
    s[threadIdx.x] = v;
    __syncthreads();
    for (int off = 1; off < 1024; off <<= 1) {
        int t = (threadIdx.x >= off) ? s[threadIdx.x - off] : 0;
        __syncthreads();
        s[threadIdx.x] += t;
        __syncthreads();
    }
    if (i < NNODES) scanbuf[i] = s[threadIdx.x];
    if (threadIdx.x == 1023) bsums[blockIdx.x] = s[1023];
}

__global__ void scan_sums_kernel() {
    __shared__ int s[128];
    int* bsums = g_bsums + blockIdx.x * 128;
    int v = (threadIdx.x < NBLK) ? bsums[threadIdx.x] : 0;
    s[threadIdx.x] = v;
    __syncthreads();
    for (int off = 1; off < 128; off <<= 1) {
        int t = (threadIdx.x >= off) ? s[threadIdx.x - off] : 0;
        __syncthreads();
        s[threadIdx.x] += t;
        __syncthreads();
    }
    if (threadIdx.x < NBLK) bsums[threadIdx.x] = s[threadIdx.x] - v;  // exclusive
}

__global__ void scan_final_kernel() {
    int sel = blockIdx.y;
    const int* deg     = sel ? g_deg_in : g_deg_out;
    const int* scanbuf = g_scan + sel * NNODES;
    const int* bsums   = g_bsums + sel * 128;
    int* rowptr        = sel ? g_rowptrAT : g_rowptrA;
    int* cursor        = sel ? g_curAT    : g_curA;
    float* nrm         = sel ? g_i : g_o;
    int i = blockIdx.x * blockDim.x + threadIdx.x;
    if (i < NNODES) {
        int d = deg[i];
        int excl = scanbuf[i] + bsums[i >> 10] - d;
        rowptr[i] = excl;
        cursor[i] = excl;
        nrm[i] = (d > 0) ? rsqrtf((float)d) : 0.0f;
    }
    if (i == 0) rowptr[NNODES] = NEDGES;
}

__global__ void fill_csr_kernel(const int* __restrict__ ei) {
    int e = blockIdx.x * blockDim.x + threadIdx.x;
    if (e < NEDGES) {
        int r = ei[e];
        int c = ei[NEDGES + e];
        int p = atomicAdd(&g_curA[r], 1);
        g_eA[p] = make_int2(c, __float_as_int(g_i[c]));
        int q = atomicAdd(&g_curAT[c], 1);
        g_eAT[q] = make_int2(r, __float_as_int(g_o[r]));
    }
}

// Build fused U [128 x 320]: rows 0..63 -> out side, 64..127 -> Z side.
__global__ void prep_U_kernel(const float* __restrict__ Wsd, const float* __restrict__ Wds,
                              const float* __restrict__ W0sd, const float* __restrict__ W0ds,
                              const float* __restrict__ bssd, const float* __restrict__ bsds,
                              const float* __restrict__ b0sd, const float* __restrict__ b0ds) {
    int t = blockIdx.x * blockDim.x + threadIdx.x;
    if (t < 128 * 320) {
        int c = t / 320;
        int kk = t - c * 320;
        int b = kk >> 6;        // block 0..4  (x, y1, y2, y3, y4)
        int k = kk & 63;
        float v;
        float coef = exp2f(-(float)b);   // 2^-b ; b>=1 blocks
        if (c < 64) {
            if (b == 0) v = 0.5f * (W0sd[c * 64 + k] + W0ds[c * 64 + k]);
            else        v = coef * Wsd[(b - 1) * 4096 + c * 64 + k];
        } else {
            int cc = c - 64;
            if (b == 0)      v = 0.5f * Wds[cc * 64 + k];
            else if (b == 1) v = 0.0f;
            else             v = coef * Wds[(b - 1) * 4096 + cc * 64 + k];
        }
        g_U[t] = v;
    }
    if (t < 64) {
        float bsum = b0sd[t] + b0ds[t];
        float sc = 1.0f;
        #pragma unroll
        for (int kk = 0; kk < 4; kk++) {
            bsum += sc * (bssd[kk * 64 + t] + bsds[kk * 64 + t]);
            sc *= 0.5f;
        }
        g_bias[t] = 0.5f * bsum;
    }
}

// ---------------- SpMM: out[r,:] (=/+=) ss[r] * sum_e val_e * h[col_e,:] ----------------
__global__ void spmm_kernel(const int* __restrict__ rowptr, const int2* __restrict__ ecv,
                            const float* __restrict__ ss, const float* __restrict__ h,
                            float* __restrict__ out, int acc) {
    int gt = blockIdx.x * blockDim.x + threadIdx.x;
    int r = gt >> 4;
    if (r >= NNODES) return;
    int lane = (gt & 15) << 2;

    int k = rowptr[r];
    int end = rowptr[r + 1];
    float a0 = 0.f, a1 = 0.f, a2 = 0.f, a3 = 0.f;
    float b0 = 0.f, b1 = 0.f, b2 = 0.f, b3 = 0.f;

    while (k + 2 <= end) {
        int2 e0 = __ldg(ecv + k);
        int2 e1 = __ldg(ecv + k + 1);
        float v0 = __int_as_float(e0.y);
        float v1 = __int_as_float(e1.y);
        const float4 h0 = __ldg((const float4*)(h + ((size_t)e0.x << 6) + lane));
        const float4 h1 = __ldg((const float4*)(h + ((size_t)e1.x << 6) + lane));
        a0 = fmaf(v0, h0.x, a0); a1 = fmaf(v0, h0.y, a1);
        a2 = fmaf(v0, h0.z, a2); a3 = fmaf(v0, h0.w, a3);
        b0 = fmaf(v1, h1.x, b0); b1 = fmaf(v1, h1.y, b1);
        b2 = fmaf(v1, h1.z, b2); b3 = fmaf(v1, h1.w, b3);
        k += 2;
    }
    if (k < end) {
        int2 e0 = __ldg(ecv + k);
        float v0 = __int_as_float(e0.y);
        const float4 h0 = __ldg((const float4*)(h + ((size_t)e0.x << 6) + lane));
        a0 = fmaf(v0, h0.x, a0); a1 = fmaf(v0, h0.y, a1);
        a2 = fmaf(v0, h0.z, a2); a3 = fmaf(v0, h0.w, a3);
    }
    a0 += b0; a1 += b1; a2 += b2; a3 += b3;

    float s = ss[r];
    size_t o = ((size_t)r << 6) + lane;
    float4 res;
    if (acc) {
        float4 p = *reinterpret_cast<float4*>(out + o);
        res.x = fmaf(s, a0, p.x); res.y = fmaf(s, a1, p.y);
        res.z = fmaf(s, a2, p.z); res.w = fmaf(s, a3, p.w);
    } else {
        res.x = s * a0; res.y = s * a1; res.z = s * a2; res.w = s * a3;
    }
    *reinterpret_cast<float4*>(out + o) = res;
}

// ---------------- Mega-GEMM: [out | Z] = [x|y1|y2|y3|y4] @ U^T  (K=320, Ncols=128) ----------------
// 128-row x 128-col block tile, 256 threads, 8x8 per thread via f32x2 packed FMA.
__global__ __launch_bounds__(256) void mega_gemm_kernel(
    const float* __restrict__ x, const float* __restrict__ y1, const float* __restrict__ y2,
    const float* __restrict__ y3, const float* __restrict__ y4,
    const float* __restrict__ U, const float* __restrict__ bias,
    float* __restrict__ out, float* __restrict__ Z)
{
    __shared__ float syT[32 * 128];   // [d][r]
    __shared__ float swT[32 * 128];   // [d][c]

    const int tid  = threadIdx.x;
    const int row0 = blockIdx.x * 128;
    const int lr   = tid & 127;
    const int half = tid >> 7;
    const int tr   = tid >> 4;        // 0..15
    const int tc   = tid & 15;        // 0..15
    const int r0   = tr * 8;

    unsigned long long acc[8][4];
    #pragma unroll
    for (int i = 0; i < 8; i++)
        #pragma unroll
        for (int j = 0; j < 4; j++) acc[i][j] = 0ull;

    const bool row_ok = (row0 + lr) < NNODES;
    const float* srcs[5] = {x, y1, y2, y3, y4};

    #pragma unroll
    for (int g = 0; g < 10; g++) {
        const float* src = srcs[g >> 1];
        const int base = (g & 1) * 32;          // column offset within 64-wide matrix

        __syncthreads();
        // stage syT: 128 rows x 32 cols (transposed)
        {
            const float4* sp = reinterpret_cast<const float4*>(src + (size_t)(row0 + lr) * 64 + base);
            #pragma unroll
            for (int q = 0; q < 4; q++) {
                int dp = half * 4 + q;
                float4 v = row_ok ? __ldg(sp + dp) : make_float4(0.f, 0.f, 0.f, 0.f);
                int d = dp << 2;
                syT[(d + 0) * 128 + lr] = v.x;
                syT[(d + 1) * 128 + lr] = v.y;
                syT[(d + 2) * 128 + lr] = v.z;
                syT[(d + 3) * 128 + lr] = v.w;
            }
        }
        // stage swT: U[c][ (g>>1)*64 + base + d ]
        {
            const float4* up = reinterpret_cast<const float4*>(U + (size_t)lr * 320 + (g >> 1) * 64 + base);
            #pragma unroll
            for (int q = 0; q < 4; q++) {
                int dp = half * 4 + q;
                float4 v = __ldg(up + dp);
                int d = dp << 2;
                swT[(d + 0) * 128 + lr] = v.x;
                swT[(d + 1) * 128 + lr] = v.y;
                swT[(d + 2) * 128 + lr] = v.z;
                swT[(d + 3) * 128 + lr] = v.w;
            }
        }
        __syncthreads();

        #pragma unroll 4
        for (int d = 0; d < 32; d++) {
            const float* sy = &syT[d * 128];
            float4 ya = *reinterpret_cast<const float4*>(sy + r0);
            float4 yb = *reinterpret_cast<const float4*>(sy + r0 + 4);
            const unsigned long long* sw = reinterpret_cast<const unsigned long long*>(&swT[d * 128]);
            unsigned long long w0 = sw[tc * 2];
            unsigned long long w1 = sw[tc * 2 + 1];
            unsigned long long w2 = sw[32 + tc * 2];
            unsigned long long w3 = sw[32 + tc * 2 + 1];
            float yr[8] = {ya.x, ya.y, ya.z, ya.w, yb.x, yb.y, yb.z, yb.w};
            #pragma unroll
            for (int i = 0; i < 8; i++) {
                unsigned long long yd = dup2(yr[i]);
                ffma2(acc[i][0], yd, w0);
                ffma2(acc[i][1], yd, w1);
                ffma2(acc[i][2], yd, w2);
                ffma2(acc[i][3], yd, w3);
            }
        }
    }

    // epilogue
    const float4 bv = *reinterpret_cast<const float4*>(bias + tc * 4);
    #pragma unroll
    for (int i = 0; i < 8; i++) {
        int r = row0 + r0 + i;
        if (r < NNODES) {
            float2 p0 = unpk(acc[i][0]);
            float2 p1 = unpk(acc[i][1]);
            float4 ov = make_float4(p0.x + bv.x, p0.y + bv.y, p1.x + bv.z, p1.y + bv.w);
            *reinterpret_cast<float4*>(out + (size_t)r * 64 + tc * 4) = ov;
            float2 q0 = unpk(acc[i][2]);
            float2 q1 = unpk(acc[i][3]);
            *reinterpret_cast<float4*>(Z + (size_t)r * 64 + tc * 4) = make_float4(q0.x, q0.y, q1.x, q1.y);
        }
    }
}

// ---------------- launch ----------------
extern "C" void kernel_launch(void* const* d_in, const int* in_sizes, int n_in,
                              void* d_out, int out_size) {
    const float* x    = (const float*)d_in[0];
    const int*   ei   = (const int*)d_in[1];
    const float* Wsd  = (const float*)d_in[2];
    const float* bssd = (const float*)d_in[3];
    const float* Wds  = (const float*)d_in[4];
    const float* bsds = (const float*)d_in[5];
    const float* W0sd = (const float*)d_in[6];
    const float* b0sd = (const float*)d_in[7];
    const float* W0ds = (const float*)d_in[8];
    const float* b0ds = (const float*)d_in[9];
    float* out = (float*)d_out;

    void* tmp;
    cudaGetSymbolAddress(&tmp, g_y1);       float* y1 = (float*)tmp;
    cudaGetSymbolAddress(&tmp, g_y2);       float* y2 = (float*)tmp;
    cudaGetSymbolAddress(&tmp, g_y3);       float* y3 = (float*)tmp;
    cudaGetSymbolAddress(&tmp, g_y4);       float* y4 = (float*)tmp;
    cudaGetSymbolAddress(&tmp, g_Z);        float* Z  = (float*)tmp;
    cudaGetSymbolAddress(&tmp, g_U);        float* U  = (float*)tmp;
    cudaGetSymbolAddress(&tmp, g_bias);     float* bias = (float*)tmp;
    cudaGetSymbolAddress(&tmp, g_rowptrA);  int* rpA  = (int*)tmp;
    cudaGetSymbolAddress(&tmp, g_rowptrAT); int* rpAT = (int*)tmp;
    cudaGetSymbolAddress(&tmp, g_eA);       int2* eA  = (int2*)tmp;
    cudaGetSymbolAddress(&tmp, g_eAT);      int2* eAT = (int2*)tmp;
    cudaGetSymbolAddress(&tmp, g_o);        float* no = (float*)tmp;
    cudaGetSymbolAddress(&tmp, g_i);        float* ni = (float*)tmp;

    const int nblk_nodes = (NNODES + 255) / 256;        // 391
    const int nblk_edges = (NEDGES + 255) / 256;        // 6250
    const int nblk_spmm  = (NNODES * 16 + 255) / 256;   // 6250
    const int nblk_gemm  = (NNODES + 127) / 128;        // 782

    // ---- preprocessing ----
    zero_deg_kernel<<<nblk_nodes, 256>>>();
    count_deg_kernel<<<nblk_edges, 256>>>(ei);
    scan_partial_kernel<<<dim3(NBLK, 2), 1024>>>();
    scan_sums_kernel<<<2, 128>>>();
    scan_final_kernel<<<dim3(nblk_nodes, 2), 256>>>();
    fill_csr_kernel<<<nblk_edges, 256>>>(ei);
    prep_U_kernel<<<160, 256>>>(Wsd, Wds, W0sd, W0ds, bssd, bsds, b0sd, b0ds);

    // ---- hop chain: y_i = A y_{i-1} ----
    spmm_kernel<<<nblk_spmm, 256>>>(rpA, eA, no, x,  y1, 0);
    spmm_kernel<<<nblk_spmm, 256>>>(rpA, eA, no, y1, y2, 0);
    spmm_kernel<<<nblk_spmm, 256>>>(rpA, eA, no, y2, y3, 0);
    spmm_kernel<<<nblk_spmm, 256>>>(rpA, eA, no, y3, y4, 0);

    // ---- single fused GEMM: out = bias + Ycat @ Usd^T ; Z = Ycat @ Uds^T ----
    mega_gemm_kernel<<<nblk_gemm, 256>>>(x, y1, y2, y3, y4, U, bias, out, Z);

    // ---- out += A^T Z (collapses all transposed-direction hops) ----
    spmm_kernel<<<nblk_spmm, 256>>>(rpAT, eAT, ni, Z, out, 1);
}

// round 3
// speedup vs baseline: 2.2997x; 1.7325x over previous
#include <cuda_runtime.h>
#include <cuda_fp16.h>
#include <mma.h>
#include <cstdint>

using namespace nvcuda;

#define NNODES 100000
#define NEDGES 1600000
#define NBLK   98          // ceil(NNODES/1024)

// ---------------- device scratch ----------------
__device__ int    g_deg_out[NNODES];
__device__ int    g_deg_in[NNODES];
__device__ float  g_o[NNODES];
__device__ float  g_i[NNODES];
__device__ int    g_rowptrA[NNODES + 1];
__device__ int    g_rowptrAT[NNODES + 1];
__device__ int    g_curA[NNODES];
__device__ int    g_curAT[NNODES];
__device__ int2   g_eA[NEDGES];     // {col, float_bits(val)}
__device__ int2   g_eAT[NEDGES];
__device__ int    g_scan[2 * NNODES];
__device__ int    g_bsums[256];
__device__ __half g_xh [(size_t)NNODES * 64];
__device__ __half g_y1h[(size_t)NNODES * 64];
__device__ __half g_y2h[(size_t)NNODES * 64];
__device__ __half g_y3h[(size_t)NNODES * 64];
__device__ __half g_y4h[(size_t)NNODES * 64];
__device__ __half g_Zh [(size_t)NNODES * 64];
__device__ float  g_bias[64];
__device__ __half g_Uh[128 * 320];  // fused weight matrix (coeffs folded), [col][k]

// ---------------- preprocessing ----------------
__global__ void zero_deg_kernel() {
    int i = blockIdx.x * blockDim.x + threadIdx.x;
    if (i < NNODES) { g_deg_out[i] = 0; g_deg_in[i] = 0; }
}

__global__ void count_deg_kernel(const int* __restrict__ ei) {
    int e = blockIdx.x * blockDim.x + threadIdx.x;
    if (e < NEDGES) {
        atomicAdd(&g_deg_out[ei[e]], 1);
        atomicAdd(&g_deg_in[ei[NEDGES + e]], 1);
    }
}

__global__ void scan_partial_kernel() {
    __shared__ int s[1024];
    int sel = blockIdx.y;
    const int* deg = sel ? g_deg_in : g_deg_out;
    int* scanbuf = g_scan + sel * NNODES;
    int* bsums   = g_bsums + sel * 128;
    int i = blockIdx.x * 1024 + threadIdx.x;
    int v = (i < NNODES) ? deg[i] : 0;
    s[threadIdx.x] = v;
    __syncthreads();
    for (int off = 1; off < 1024; off <<= 1) {
        int t = (threadIdx.x >= off) ? s[threadIdx.x - off] : 0;
        __syncthreads();
        s[threadIdx.x] += t;
        __syncthreads();
    }
    if (i < NNODES) scanbuf[i] = s[threadIdx.x];
    if (threadIdx.x == 1023) bsums[blockIdx.x] = s[1023];
}

__global__ void scan_sums_kernel() {
    __shared__ int s[128];
    int* bsums = g_bsums + blockIdx.x * 128;
    int v = (threadIdx.x < NBLK) ? bsums[threadIdx.x] : 0;
    s[threadIdx.x] = v;
    __syncthreads();
    for (int off = 1; off < 128; off <<= 1) {
        int t = (threadIdx.x >= off) ? s[threadIdx.x - off] : 0;
        __syncthreads();
        s[threadIdx.x] += t;
        __syncthreads();
    }
    if (threadIdx.x < NBLK) bsums[threadIdx.x] = s[threadIdx.x] - v;  // exclusive
}

__global__ void scan_final_kernel() {
    int sel = blockIdx.y;
    const int* deg     = sel ? g_deg_in : g_deg_out;
    const int* scanbuf = g_scan + sel * NNODES;
    const int* bsums   = g_bsums + sel * 128;
    int* rowptr        = sel ? g_rowptrAT : g_rowptrA;
    int* cursor        = sel ? g_curAT    : g_curA;
    float* nrm         = sel ? g_i : g_o;
    int i = blockIdx.x * blockDim.x + threadIdx.x;
    if (i < NNODES) {
        int d = deg[i];
        int excl = scanbuf[i] + bsums[i >> 10] - d;
        rowptr[i] = excl;
        cursor[i] = excl;
        nrm[i] = (d > 0) ? rsqrtf((float)d) : 0.0f;
    }
    if (i == 0) rowptr[NNODES] = NEDGES;
}

__global__ void fill_csr_kernel(const int* __restrict__ ei) {
    int e = blockIdx.x * blockDim.x + threadIdx.x;
    if (e < NEDGES) {
        int r = ei[e];
        int c = ei[NEDGES + e];
        int p = atomicAdd(&g_curA[r], 1);
        g_eA[p] = make_int2(c, __float_as_int(g_i[c]));
        int q = atomicAdd(&g_curAT[c], 1);
        g_eAT[q] = make_int2(r, __float_as_int(g_o[r]));
    }
}

// Build fused Uh [128 cols][320 k] fp16; rows 0..63 -> out side, 64..127 -> Z side.
__global__ void prep_U_kernel(const float* __restrict__ Wsd, const float* __restrict__ Wds,
                              const float* __restrict__ W0sd, const float* __restrict__ W0ds,
                              const float* __restrict__ bssd, const float* __restrict__ bsds,
                              const float* __restrict__ b0sd, const float* __restrict__ b0ds) {
    int t = blockIdx.x * blockDim.x + threadIdx.x;
    if (t < 128 * 320) {
        int c = t / 320;
        int kk = t - c * 320;
        int b = kk >> 6;        // block 0..4  (x, y1, y2, y3, y4)
        int k = kk & 63;
        float v;
        float coef = exp2f(-(float)b);
        if (c < 64) {
            if (b == 0) v = 0.5f * (W0sd[c * 64 + k] + W0ds[c * 64 + k]);
            else        v = coef * Wsd[(b - 1) * 4096 + c * 64 + k];
        } else {
            int cc = c - 64;
            if (b == 0)      v = 0.5f * Wds[cc * 64 + k];
            else if (b == 1) v = 0.0f;
            else             v = coef * Wds[(b - 1) * 4096 + cc * 64 + k];
        }
        g_Uh[t] = __float2half(v);
    }
    if (t < 64) {
        float bsum = b0sd[t] + b0ds[t];
        float sc = 1.0f;
        #pragma unroll
        for (int kk = 0; kk < 4; kk++) {
            bsum += sc * (bssd[kk * 64 + t] + bsds[kk * 64 + t]);
            sc *= 0.5f;
        }
        g_bias[t] = 0.5f * bsum;
    }
}

__global__ void cvt_x_kernel(const float* __restrict__ x) {
    int i = blockIdx.x * blockDim.x + threadIdx.x;    // one per 4 elems
    if (i < NNODES * 16) {
        float4 v = __ldg((const float4*)x + i);
        __half2 h0 = __floats2half2_rn(v.x, v.y);
        __half2 h1 = __floats2half2_rn(v.z, v.w);
        uint2 o;
        o.x = *reinterpret_cast<unsigned*>(&h0);
        o.y = *reinterpret_cast<unsigned*>(&h1);
        *((uint2*)g_xh + i) = o;
    }
}

// ---------------- SpMM (fp16 gather, fp32 accumulate) ----------------
// mode 0: yout[r,:] = ss[r] * sum (fp16 write)
// mode 1: outf[r,:] += bias + ss[r] * sum (fp32 RMW)
__global__ void spmm_kernel(const int* __restrict__ rowptr, const int2* __restrict__ ecv,
                            const float* __restrict__ ss, const __half* __restrict__ h,
                            __half* __restrict__ yout, float* __restrict__ outf,
                            const float* __restrict__ bias, int mode) {
    int gt = blockIdx.x * blockDim.x + threadIdx.x;
    int r = gt >> 4;
    if (r >= NNODES) return;
    int lane = gt & 15;

    int k = rowptr[r];
    int end = rowptr[r + 1];
    float a0 = 0.f, a1 = 0.f, a2 = 0.f, a3 = 0.f;
    float b0 = 0.f, b1 = 0.f, b2 = 0.f, b3 = 0.f;

    const __half* hl = h + (lane << 2);
    while (k + 2 <= end) {
        int2 e0 = __ldg(ecv + k);
        int2 e1 = __ldg(ecv + k + 1);
        float v0 = __int_as_float(e0.y);
        float v1 = __int_as_float(e1.y);
        uint2 h0 = __ldg((const uint2*)(hl + ((size_t)e0.x << 6)));
        uint2 h1 = __ldg((const uint2*)(hl + ((size_t)e1.x << 6)));
        float2 f00 = __half22float2(*reinterpret_cast<__half2*>(&h0.x));
        float2 f01 = __half22float2(*reinterpret_cast<__half2*>(&h0.y));
        float2 f10 = __half22float2(*reinterpret_cast<__half2*>(&h1.x));
        float2 f11 = __half22float2(*reinterpret_cast<__half2*>(&h1.y));
        a0 = fmaf(v0, f00.x, a0); a1 = fmaf(v0, f00.y, a1);
        a2 = fmaf(v0, f01.x, a2); a3 = fmaf(v0, f01.y, a3);
        b0 = fmaf(v1, f10.x, b0); b1 = fmaf(v1, f10.y, b1);
        b2 = fmaf(v1, f11.x, b2); b3 = fmaf(v1, f11.y, b3);
        k += 2;
    }
    if (k < end) {
        int2 e0 = __ldg(ecv + k);
        float v0 = __int_as_float(e0.y);
        uint2 h0 = __ldg((const uint2*)(hl + ((size_t)e0.x << 6)));
        float2 f00 = __half22float2(*reinterpret_cast<__half2*>(&h0.x));
        float2 f01 = __half22float2(*reinterpret_cast<__half2*>(&h0.y));
        a0 = fmaf(v0, f00.x, a0); a1 = fmaf(v0, f00.y, a1);
        a2 = fmaf(v0, f01.x, a2); a3 = fmaf(v0, f01.y, a3);
    }
    a0 += b0; a1 += b1; a2 += b2; a3 += b3;

    float s = ss[r];
    if (mode == 0) {
        __half2 o0 = __floats2half2_rn(s * a0, s * a1);
        __half2 o1 = __floats2half2_rn(s * a2, s * a3);
        uint2 o;
        o.x = *reinterpret_cast<unsigned*>(&o0);
        o.y = *reinterpret_cast<unsigned*>(&o1);
        *(uint2*)(yout + ((size_t)r << 6) + (lane << 2)) = o;
    } else {
        size_t off = ((size_t)r << 6) + (lane << 2);
        float4 p = *reinterpret_cast<float4*>(outf + off);
        float4 bv = *reinterpret_cast<const float4*>(bias + (lane << 2));
        float4 res;
        res.x = p.x + bv.x + s * a0;
        res.y = p.y + bv.y + s * a1;
        res.z = p.z + bv.z + s * a2;
        res.w = p.w + bv.w + s * a3;
        *reinterpret_cast<float4*>(outf + off) = res;
    }
}

// ---------------- Mega-GEMM via HMMA: [out | Z] = [x|y1..y4] @ U^T, K=320 ----------------
// Block: 128 rows x 128 cols, 256 threads = 8 warps in 4(row) x 2(col) grid.
// Warp tile 32 x 64. cols 0..63 -> out (fp32 direct store), 64..127 -> Z (fp16 via patch).
#define LDS_K 40
__global__ __launch_bounds__(256) void mega_gemm_kernel(
    const __half* __restrict__ xh,
    float* __restrict__ out, __half* __restrict__ Zh)
{
    __shared__ __half sA[128 * LDS_K];
    __shared__ __half sB[128 * LDS_K];
    __shared__ float patch[8][16 * 16];

    const int tid  = threadIdx.x;
    const int wid  = tid >> 5;
    const int row0 = blockIdx.x * 128;
    const int wr   = wid & 3;        // warp row 0..3
    const int wc   = wid >> 2;       // warp col 0..1

    wmma::fragment<wmma::accumulator, 16, 16, 16, float> acc[2][4];
    #pragma unroll
    for (int i = 0; i < 2; i++)
        #pragma unroll
        for (int j = 0; j < 4; j++) wmma::fill_fragment(acc[i][j], 0.0f);

    const __half* srcs[5] = {xh, g_y1h, g_y2h, g_y3h, g_y4h};

    const int srow  = tid >> 1;       // 0..127
    const int spart = (tid & 1) * 16; // half offset

    #pragma unroll
    for (int g = 0; g < 10; g++) {
        const __half* src = srcs[g >> 1];
        const int kbase = (g & 1) * 32;

        __syncthreads();
        // stage A: 128 rows x 32 k (fp16)
        {
            int grow = row0 + srow;
            uint4 v0 = make_uint4(0, 0, 0, 0), v1 = v0;
            if (grow < NNODES) {
                const uint4* p = (const uint4*)(src + (size_t)grow * 64 + kbase + spart);
                v0 = __ldg(p);
                v1 = __ldg(p + 1);
            }
            *(uint4*)&sA[srow * LDS_K + spart]     = v0;
            *(uint4*)&sA[srow * LDS_K + spart + 8] = v1;
        }
        // stage B: 128 cols x 32 k from Uh[col][k]
        {
            const uint4* p = (const uint4*)(g_Uh + (size_t)srow * 320 + (g >> 1) * 64 + kbase + spart);
            uint4 v0 = __ldg(p);
            uint4 v1 = __ldg(p + 1);
            *(uint4*)&sB[srow * LDS_K + spart]     = v0;
            *(uint4*)&sB[srow * LDS_K + spart + 8] = v1;
        }
        __syncthreads();

        #pragma unroll
        for (int ks = 0; ks < 32; ks += 16) {
            wmma::fragment<wmma::matrix_a, 16, 16, 16, __half, wmma::row_major> af[2];
            wmma::load_matrix_sync(af[0], &sA[(wr * 32 +  0) * LDS_K + ks], LDS_K);
            wmma::load_matrix_sync(af[1], &sA[(wr * 32 + 16) * LDS_K + ks], LDS_K);
            #pragma unroll
            for (int j = 0; j < 4; j++) {
                wmma::fragment<wmma::matrix_b, 16, 16, 16, __half, wmma::col_major> bf;
                wmma::load_matrix_sync(bf, &sB[(wc * 64 + j * 16) * LDS_K + ks], LDS_K);
                wmma::mma_sync(acc[0][j], af[0], bf, acc[0][j]);
                wmma::mma_sync(acc[1][j], af[1], bf, acc[1][j]);
            }
        }
    }

    // epilogue
    const int lane = tid & 31;
    #pragma unroll
    for (int i = 0; i < 2; i++) {
        int rbase = row0 + wr * 32 + i * 16;
        if (rbase >= NNODES) continue;   // frag fully in or out (NNODES % 16 == 0)
        if (wc == 0) {
            #pragma unroll
            for (int j = 0; j < 4; j++)
                wmma::store_matrix_sync(out + (size_t)rbase * 64 + j * 16,
                                        acc[i][j], 64, wmma::mem_row_major);
        } else {
            #pragma unroll
            for (int j = 0; j < 4; j++) {
                wmma::store_matrix_sync(patch[wid], acc[i][j], 16, wmma::mem_row_major);
                __syncwarp();
                int pr = lane >> 1;
                int pc = (lane & 1) * 8;
                const float* pp = &patch[wid][pr * 16 + pc];
                __half2 h0 = __floats2half2_rn(pp[0], pp[1]);
                __half2 h1 = __floats2half2_rn(pp[2], pp[3]);
                __half2 h2 = __floats2half2_rn(pp[4], pp[5]);
                __half2 h3 = __floats2half2_rn(pp[6], pp[7]);
                uint4 o;
                o.x = *reinterpret_cast<unsigned*>(&h0);
                o.y = *reinterpret_cast<unsigned*>(&h1);
                o.z = *reinterpret_cast<unsigned*>(&h2);
                o.w = *reinterpret_cast<unsigned*>(&h3);
                *(uint4*)(Zh + (size_t)(rbase + pr) * 64 + j * 16 + pc) = o;
                __syncwarp();
            }
        }
    }
}

// ---------------- launch ----------------
extern "C" void kernel_launch(void* const* d_in, const int* in_sizes, int n_in,
                              void* d_out, int out_size) {
    const float* x    = (const float*)d_in[0];
    const int*   ei   = (const int*)d_in[1];
    const float* Wsd  = (const float*)d_in[2];
    const float* bssd = (const float*)d_in[3];
    const float* Wds  = (const float*)d_in[4];
    const float* bsds = (const float*)d_in[5];
    const float* W0sd = (const float*)d_in[6];
    const float* b0sd = (const float*)d_in[7];
    const float* W0ds = (const float*)d_in[8];
    const float* b0ds = (const float*)d_in[9];
    float* out = (float*)d_out;

    void* tmp;
    cudaGetSymbolAddress(&tmp, g_xh);       __half* xh  = (__half*)tmp;
    cudaGetSymbolAddress(&tmp, g_y1h);      __half* y1h = (__half*)tmp;
    cudaGetSymbolAddress(&tmp, g_y2h);      __half* y2h = (__half*)tmp;
    cudaGetSymbolAddress(&tmp, g_y3h);      __half* y3h = (__half*)tmp;
    cudaGetSymbolAddress(&tmp, g_y4h);      __half* y4h = (__half*)tmp;
    cudaGetSymbolAddress(&tmp, g_Zh);       __half* Zh  = (__half*)tmp;
    cudaGetSymbolAddress(&tmp, g_bias);     float* bias = (float*)tmp;
    cudaGetSymbolAddress(&tmp, g_rowptrA);  int* rpA  = (int*)tmp;
    cudaGetSymbolAddress(&tmp, g_rowptrAT); int* rpAT = (int*)tmp;
    cudaGetSymbolAddress(&tmp, g_eA);       int2* eA  = (int2*)tmp;
    cudaGetSymbolAddress(&tmp, g_eAT);      int2* eAT = (int2*)tmp;
    cudaGetSymbolAddress(&tmp, g_o);        float* no = (float*)tmp;
    cudaGetSymbolAddress(&tmp, g_i);        float* ni = (float*)tmp;

    const int nblk_nodes = (NNODES + 255) / 256;        // 391
    const int nblk_edges = (NEDGES + 255) / 256;        // 6250
    const int nblk_spmm  = (NNODES * 16 + 255) / 256;   // 6250
    const int nblk_gemm  = (NNODES + 127) / 128;        // 782

    // ---- preprocessing ----
    zero_deg_kernel<<<nblk_nodes, 256>>>();
    count_deg_kernel<<<nblk_edges, 256>>>(ei);
    scan_partial_kernel<<<dim3(NBLK, 2), 1024>>>();
    scan_sums_kernel<<<2, 128>>>();
    scan_final_kernel<<<dim3(nblk_nodes, 2), 256>>>();
    fill_csr_kernel<<<nblk_edges, 256>>>(ei);
    prep_U_kernel<<<160, 256>>>(Wsd, Wds, W0sd, W0ds, bssd, bsds, b0sd, b0ds);
    cvt_x_kernel<<<nblk_spmm, 256>>>(x);

    // ---- hop chain: y_i = A y_{i-1} (all fp16 features) ----
    spmm_kernel<<<nblk_spmm, 256>>>(rpA, eA, no, xh,  y1h, nullptr, nullptr, 0);
    spmm_kernel<<<nblk_spmm, 256>>>(rpA, eA, no, y1h, y2h, nullptr, nullptr, 0);
    spmm_kernel<<<nblk_spmm, 256>>>(rpA, eA, no, y2h, y3h, nullptr, nullptr, 0);
    spmm_kernel<<<nblk_spmm, 256>>>(rpA, eA, no, y3h, y4h, nullptr, nullptr, 0);

    // ---- fused HMMA GEMM: out = Ycat @ Usd^T ; Zh = Ycat @ Uds^T ----
    mega_gemm_kernel<<<nblk_gemm, 256>>>(xh, out, Zh);

    // ---- out += bias + A^T Z ----
    spmm_kernel<<<nblk_spmm, 256>>>(rpAT, eAT, ni, Zh, nullptr, out, bias, 1);
}

// round 4
// speedup vs baseline: 2.3551x; 1.0241x over previous
#include <cuda_runtime.h>
#include <cuda_fp16.h>
#include <mma.h>
#include <cstdint>

using namespace nvcuda;

#define NNODES 100000
#define NEDGES 1600000
#define NSCANBLK 98        // ceil(NNODES/1024)

// ---------------- device scratch ----------------
__device__ int    g_deg_out[NNODES];
__device__ int    g_deg_in[NNODES];
__device__ float  g_o[NNODES];
__device__ float  g_i[NNODES];
__device__ int    g_rowptrA[NNODES + 1];
__device__ int    g_rowptrAT[NNODES + 1];
__device__ int    g_curA[NNODES];
__device__ int    g_curAT[NNODES];
__device__ int2   g_eA[NEDGES];     // {col, float_bits(val)}
__device__ int2   g_eAT[NEDGES];
__device__ unsigned long long g_tstat[2][NSCANBLK];  // decoupled-lookback status
__device__ __half g_xh [(size_t)NNODES * 64];
__device__ __half g_y1h[(size_t)NNODES * 64];
__device__ __half g_y2h[(size_t)NNODES * 64];
__device__ __half g_y3h[(size_t)NNODES * 64];
__device__ __half g_y4h[(size_t)NNODES * 64];
__device__ __half g_Zh [(size_t)NNODES * 64];
__device__ float  g_bias[64];
__device__ __half g_Uh[128 * 320];  // fused weight matrix (coeffs folded), [col][k]

// ---------------- fused init: zero degs/status + cvt x->fp16 + build U/bias ----------------
__global__ void init_kernel(const float* __restrict__ x,
                            const float* __restrict__ Wsd, const float* __restrict__ Wds,
                            const float* __restrict__ W0sd, const float* __restrict__ W0ds,
                            const float* __restrict__ bssd, const float* __restrict__ bsds,
                            const float* __restrict__ b0sd, const float* __restrict__ b0ds) {
    int t = blockIdx.x * blockDim.x + threadIdx.x;

    if (t < NNODES * 16) {          // x -> fp16, 4 elems per thread
        float4 v = __ldg((const float4*)x + t);
        __half2 h0 = __floats2half2_rn(v.x, v.y);
        __half2 h1 = __floats2half2_rn(v.z, v.w);
        uint2 o;
        o.x = *reinterpret_cast<unsigned*>(&h0);
        o.y = *reinterpret_cast<unsigned*>(&h1);
        *((uint2*)g_xh + t) = o;
    }
    if (t < NNODES) { g_deg_out[t] = 0; g_deg_in[t] = 0; }
    if (t < 2 * NSCANBLK) g_tstat[t >= NSCANBLK][t % NSCANBLK] = 0ull;

    if (t < 128 * 320) {            // fused weight matrix
        int c = t / 320;
        int kk = t - c * 320;
        int b = kk >> 6;            // block 0..4  (x, y1, y2, y3, y4)
        int k = kk & 63;
        float v;
        float coef = exp2f(-(float)b);
        if (c < 64) {
            if (b == 0) v = 0.5f * (W0sd[c * 64 + k] + W0ds[c * 64 + k]);
            else        v = coef * Wsd[(b - 1) * 4096 + c * 64 + k];
        } else {
            int cc = c - 64;
            if (b == 0)      v = 0.5f * Wds[cc * 64 + k];
            else if (b == 1) v = 0.0f;
            else             v = coef * Wds[(b - 1) * 4096 + cc * 64 + k];
        }
        g_Uh[t] = __float2half(v);
    }
    if (t < 64) {
        float bsum = b0sd[t] + b0ds[t];
        float sc = 1.0f;
        #pragma unroll
        for (int kk = 0; kk < 4; kk++) {
            bsum += sc * (bssd[kk * 64 + t] + bsds[kk * 64 + t]);
            sc *= 0.5f;
        }
        g_bias[t] = 0.5f * bsum;
    }
}

__global__ void count_deg_kernel(const int* __restrict__ ei) {
    int e = blockIdx.x * blockDim.x + threadIdx.x;
    if (e < NEDGES) {
        atomicAdd(&g_deg_out[ei[e]], 1);
        atomicAdd(&g_deg_in[ei[NEDGES + e]], 1);
    }
}

// ---------------- single-pass exclusive scan (decoupled lookback) ----------------
// Also produces rowptr, cursor, and rsqrt norms in one kernel.
__global__ void scan_lookback_kernel() {
    __shared__ int s[1024];
    __shared__ int s_prefix;
    const int sel = blockIdx.y;
    const int* deg = sel ? g_deg_in : g_deg_out;
    unsigned long long* tstat = g_tstat[sel];
    int* rowptr = sel ? g_rowptrAT : g_rowptrA;
    int* cursor = sel ? g_curAT : g_curA;
    float* nrm  = sel ? g_i : g_o;

    const int tid = threadIdx.x;
    const int i = blockIdx.x * 1024 + tid;
    int v = (i < NNODES) ? deg[i] : 0;
    s[tid] = v;
    __syncthreads();
    #pragma unroll
    for (int off = 1; off < 1024; off <<= 1) {
        int t = (tid >= off) ? s[tid - off] : 0;
        __syncthreads();
        s[tid] += t;
        __syncthreads();
    }
    int incl = s[tid];
    int aggregate = s[1023];

    if (tid == 0) {
        if (blockIdx.x == 0) {
            atomicExch(&tstat[0], (2ull << 32) | (unsigned)aggregate);
            s_prefix = 0;
        } else {
            atomicExch(&tstat[blockIdx.x], (1ull << 32) | (unsigned)aggregate);
            int pfx = 0;
            int j = blockIdx.x - 1;
            for (;;) {
                unsigned long long st;
                do { st = atomicAdd(&tstat[j], 0ull); } while ((st >> 32) == 0ull);
                pfx += (int)(unsigned)st;
                if ((st >> 32) == 2ull) break;
                j--;
            }
            atomicExch(&tstat[blockIdx.x], (2ull << 32) | (unsigned)(aggregate + pfx));
            s_prefix = pfx;
        }
    }
    __syncthreads();

    if (i < NNODES) {
        int excl = s_prefix + incl - v;
        rowptr[i] = excl;
        cursor[i] = excl;
        nrm[i] = (v > 0) ? rsqrtf((float)v) : 0.0f;
    }
    if (i == 0) rowptr[NNODES] = NEDGES;
}

__global__ void fill_csr_kernel(const int* __restrict__ ei) {
    int e = blockIdx.x * blockDim.x + threadIdx.x;
    if (e < NEDGES) {
        int r = ei[e];
        int c = ei[NEDGES + e];
        int p = atomicAdd(&g_curA[r], 1);
        g_eA[p] = make_int2(c, __float_as_int(g_i[c]));
        int q = atomicAdd(&g_curAT[c], 1);
        g_eAT[q] = make_int2(r, __float_as_int(g_o[r]));
    }
}

// ---------------- SpMM (fp16 gather, fp32 accumulate) ----------------
// 8 lanes per row, 8 features (16B) per lane, unroll-2 for MLP.
// mode 0: yout[r,:] = ss[r] * sum (fp16 write)
// mode 1: outf[r,:] += bias + ss[r] * sum (fp32 RMW)
__global__ void spmm_kernel(const int* __restrict__ rowptr, const int2* __restrict__ ecv,
                            const float* __restrict__ ss, const __half* __restrict__ h,
                            __half* __restrict__ yout, float* __restrict__ outf,
                            const float* __restrict__ bias, int mode) {
    int gt = blockIdx.x * blockDim.x + threadIdx.x;
    int r = gt >> 3;
    if (r >= NNODES) return;
    int lane = gt & 7;

    int k = rowptr[r];
    int end = rowptr[r + 1];
    float a[8] = {0.f, 0.f, 0.f, 0.f, 0.f, 0.f, 0.f, 0.f};
    float b[8] = {0.f, 0.f, 0.f, 0.f, 0.f, 0.f, 0.f, 0.f};

    const __half* hl = h + (lane << 3);
    while (k + 2 <= end) {
        int2 e0 = __ldg(ecv + k);
        int2 e1 = __ldg(ecv + k + 1);
        float v0 = __int_as_float(e0.y);
        float v1 = __int_as_float(e1.y);
        uint4 h0 = __ldg((const uint4*)(hl + ((size_t)e0.x << 6)));
        uint4 h1 = __ldg((const uint4*)(hl + ((size_t)e1.x << 6)));
        const unsigned* p0 = &h0.x;
        const unsigned* p1 = &h1.x;
        #pragma unroll
        for (int q = 0; q < 4; q++) {
            float2 f0 = __half22float2(*reinterpret_cast<const __half2*>(p0 + q));
            float2 f1 = __half22float2(*reinterpret_cast<const __half2*>(p1 + q));
            a[q * 2]     = fmaf(v0, f0.x, a[q * 2]);
            a[q * 2 + 1] = fmaf(v0, f0.y, a[q * 2 + 1]);
            b[q * 2]     = fmaf(v1, f1.x, b[q * 2]);
            b[q * 2 + 1] = fmaf(v1, f1.y, b[q * 2 + 1]);
        }
        k += 2;
    }
    if (k < end) {
        int2 e0 = __ldg(ecv + k);
        float v0 = __int_as_float(e0.y);
        uint4 h0 = __ldg((const uint4*)(hl + ((size_t)e0.x << 6)));
        const unsigned* p0 = &h0.x;
        #pragma unroll
        for (int q = 0; q < 4; q++) {
            float2 f0 = __half22float2(*reinterpret_cast<const __half2*>(p0 + q));
            a[q * 2]     = fmaf(v0, f0.x, a[q * 2]);
            a[q * 2 + 1] = fmaf(v0, f0.y, a[q * 2 + 1]);
        }
    }
    #pragma unroll
    for (int q = 0; q < 8; q++) a[q] += b[q];

    float s = ss[r];
    if (mode == 0) {
        uint4 o;
        __half2 h0 = __floats2half2_rn(s * a[0], s * a[1]);
        __half2 h1 = __floats2half2_rn(s * a[2], s * a[3]);
        __half2 h2 = __floats2half2_rn(s * a[4], s * a[5]);
        __half2 h3 = __floats2half2_rn(s * a[6], s * a[7]);
        o.x = *reinterpret_cast<unsigned*>(&h0);
        o.y = *reinterpret_cast<unsigned*>(&h1);
        o.z = *reinterpret_cast<unsigned*>(&h2);
        o.w = *reinterpret_cast<unsigned*>(&h3);
        *(uint4*)(yout + ((size_t)r << 6) + (lane << 3)) = o;
    } else {
        size_t off = ((size_t)r << 6) + (lane << 3);
        float4 p0 = *reinterpret_cast<float4*>(outf + off);
        float4 p1 = *reinterpret_cast<float4*>(outf + off + 4);
        float4 bv0 = *reinterpret_cast<const float4*>(bias + (lane << 3));
        float4 bv1 = *reinterpret_cast<const float4*>(bias + (lane << 3) + 4);
        float4 r0, r1;
        r0.x = p0.x + bv0.x + s * a[0];
        r0.y = p0.y + bv0.y + s * a[1];
        r0.z = p0.z + bv0.z + s * a[2];
        r0.w = p0.w + bv0.w + s * a[3];
        r1.x = p1.x + bv1.x + s * a[4];
        r1.y = p1.y + bv1.y + s * a[5];
        r1.z = p1.z + bv1.z + s * a[6];
        r1.w = p1.w + bv1.w + s * a[7];
        *reinterpret_cast<float4*>(outf + off)     = r0;
        *reinterpret_cast<float4*>(outf + off + 4) = r1;
    }
}

// ---------------- Mega-GEMM via HMMA: [out | Z] = [x|y1..y4] @ U^T, K=320 ----------------
#define LDS_K 40
__global__ __launch_bounds__(256) void mega_gemm_kernel(
    const __half* __restrict__ xh,
    float* __restrict__ out, __half* __restrict__ Zh)
{
    __shared__ __half sA[128 * LDS_K];
    __shared__ __half sB[128 * LDS_K];
    __shared__ float patch[8][16 * 16];

    const int tid  = threadIdx.x;
    const int wid  = tid >> 5;
    const int row0 = blockIdx.x * 128;
    const int wr   = wid & 3;
    const int wc   = wid >> 2;

    wmma::fragment<wmma::accumulator, 16, 16, 16, float> acc[2][4];
    #pragma unroll
    for (int i = 0; i < 2; i++)
        #pragma unroll
        for (int j = 0; j < 4; j++) wmma::fill_fragment(acc[i][j], 0.0f);

    const __half* srcs[5] = {xh, g_y1h, g_y2h, g_y3h, g_y4h};

    const int srow  = tid >> 1;
    const int spart = (tid & 1) * 16;

    #pragma unroll
    for (int g = 0; g < 10; g++) {
        const __half* src = srcs[g >> 1];
        const int kbase = (g & 1) * 32;

        __syncthreads();
        {
            int grow = row0 + srow;
            uint4 v0 = make_uint4(0, 0, 0, 0), v1 = v0;
            if (grow < NNODES) {
                const uint4* p = (const uint4*)(src + (size_t)grow * 64 + kbase + spart);
                v0 = __ldg(p);
                v1 = __ldg(p + 1);
            }
            *(uint4*)&sA[srow * LDS_K + spart]     = v0;
            *(uint4*)&sA[srow * LDS_K + spart + 8] = v1;
        }
        {
            const uint4* p = (const uint4*)(g_Uh + (size_t)srow * 320 + (g >> 1) * 64 + kbase + spart);
            uint4 v0 = __ldg(p);
            uint4 v1 = __ldg(p + 1);
            *(uint4*)&sB[srow * LDS_K + spart]     = v0;
            *(uint4*)&sB[srow * LDS_K + spart + 8] = v1;
        }
        __syncthreads();

        #pragma unroll
        for (int ks = 0; ks < 32; ks += 16) {
            wmma::fragment<wmma::matrix_a, 16, 16, 16, __half, wmma::row_major> af[2];
            wmma::load_matrix_sync(af[0], &sA[(wr * 32 +  0) * LDS_K + ks], LDS_K);
            wmma::load_matrix_sync(af[1], &sA[(wr * 32 + 16) * LDS_K + ks], LDS_K);
            #pragma unroll
            for (int j = 0; j < 4; j++) {
                wmma::fragment<wmma::matrix_b, 16, 16, 16, __half, wmma::col_major> bf;
                wmma::load_matrix_sync(bf, &sB[(wc * 64 + j * 16) * LDS_K + ks], LDS_K);
                wmma::mma_sync(acc[0][j], af[0], bf, acc[0][j]);
                wmma::mma_sync(acc[1][j], af[1], bf, acc[1][j]);
            }
        }
    }

    const int lane = tid & 31;
    #pragma unroll
    for (int i = 0; i < 2; i++) {
        int rbase = row0 + wr * 32 + i * 16;
        if (rbase >= NNODES) continue;
        if (wc == 0) {
            #pragma unroll
            for (int j = 0; j < 4; j++)
                wmma::store_matrix_sync(out + (size_t)rbase * 64 + j * 16,
                                        acc[i][j], 64, wmma::mem_row_major);
        } else {
            #pragma unroll
            for (int j = 0; j < 4; j++) {
                wmma::store_matrix_sync(patch[wid], acc[i][j], 16, wmma::mem_row_major);
                __syncwarp();
                int pr = lane >> 1;
                int pc = (lane & 1) * 8;
                const float* pp = &patch[wid][pr * 16 + pc];
                __half2 h0 = __floats2half2_rn(pp[0], pp[1]);
                __half2 h1 = __floats2half2_rn(pp[2], pp[3]);
                __half2 h2 = __floats2half2_rn(pp[4], pp[5]);
                __half2 h3 = __floats2half2_rn(pp[6], pp[7]);
                uint4 o;
                o.x = *reinterpret_cast<unsigned*>(&h0);
                o.y = *reinterpret_cast<unsigned*>(&h1);
                o.z = *reinterpret_cast<unsigned*>(&h2);
                o.w = *reinterpret_cast<unsigned*>(&h3);
                *(uint4*)(Zh + (size_t)(rbase + pr) * 64 + j * 16 + pc) = o;
                __syncwarp();
            }
        }
    }
}

// ---------------- launch ----------------
extern "C" void kernel_launch(void* const* d_in, const int* in_sizes, int n_in,
                              void* d_out, int out_size) {
    const float* x    = (const float*)d_in[0];
    const int*   ei   = (const int*)d_in[1];
    const float* Wsd  = (const float*)d_in[2];
    const float* bssd = (const float*)d_in[3];
    const float* Wds  = (const float*)d_in[4];
    const float* bsds = (const float*)d_in[5];
    const float* W0sd = (const float*)d_in[6];
    const float* b0sd = (const float*)d_in[7];
    const float* W0ds = (const float*)d_in[8];
    const float* b0ds = (const float*)d_in[9];
    float* out = (float*)d_out;

    void* tmp;
    cudaGetSymbolAddress(&tmp, g_xh);       __half* xh  = (__half*)tmp;
    cudaGetSymbolAddress(&tmp, g_y1h);      __half* y1h = (__half*)tmp;
    cudaGetSymbolAddress(&tmp, g_y2h);      __half* y2h = (__half*)tmp;
    cudaGetSymbolAddress(&tmp, g_y3h);      __half* y3h = (__half*)tmp;
    cudaGetSymbolAddress(&tmp, g_y4h);      __half* y4h = (__half*)tmp;
    cudaGetSymbolAddress(&tmp, g_Zh);       __half* Zh  = (__half*)tmp;
    cudaGetSymbolAddress(&tmp, g_bias);     float* bias = (float*)tmp;
    cudaGetSymbolAddress(&tmp, g_rowptrA);  int* rpA  = (int*)tmp;
    cudaGetSymbolAddress(&tmp, g_rowptrAT); int* rpAT = (int*)tmp;
    cudaGetSymbolAddress(&tmp, g_eA);       int2* eA  = (int2*)tmp;
    cudaGetSymbolAddress(&tmp, g_eAT);      int2* eAT = (int2*)tmp;
    cudaGetSymbolAddress(&tmp, g_o);        float* no = (float*)tmp;
    cudaGetSymbolAddress(&tmp, g_i);        float* ni = (float*)tmp;

    const int nblk_init  = (NNODES * 16 + 255) / 256;   // 6250 (covers all init work)
    const int nblk_edges = (NEDGES + 255) / 256;        // 6250
    const int nblk_spmm  = (NNODES * 8 + 255) / 256;    // 3125
    const int nblk_gemm  = (NNODES + 127) / 128;        // 782

    // ---- preprocessing (4 launches) ----
    init_kernel<<<nblk_init, 256>>>(x, Wsd, Wds, W0sd, W0ds, bssd, bsds, b0sd, b0ds);
    count_deg_kernel<<<nblk_edges, 256>>>(ei);
    scan_lookback_kernel<<<dim3(NSCANBLK, 2), 1024>>>();
    fill_csr_kernel<<<nblk_edges, 256>>>(ei);

    // ---- hop chain: y_i = A y_{i-1} (fp16 features) ----
    spmm_kernel<<<nblk_spmm, 256>>>(rpA, eA, no, xh,  y1h, nullptr, nullptr, 0);
    spmm_kernel<<<nblk_spmm, 256>>>(rpA, eA, no, y1h, y2h, nullptr, nullptr, 0);
    spmm_kernel<<<nblk_spmm, 256>>>(rpA, eA, no, y2h, y3h, nullptr, nullptr, 0);
    spmm_kernel<<<nblk_spmm, 256>>>(rpA, eA, no, y3h, y4h, nullptr, nullptr, 0);

    // ---- fused HMMA GEMM: out = Ycat @ Usd^T ; Zh = Ycat @ Uds^T ----
    mega_gemm_kernel<<<nblk_gemm, 256>>>(xh, out, Zh);

    // ---- out += bias + A^T Z ----
    spmm_kernel<<<nblk_spmm, 256>>>(rpAT, eAT, ni, Zh, nullptr, out, bias, 1);
}

// round 5
// speedup vs baseline: 2.6286x; 1.1162x over previous
#include <cuda_runtime.h>
#include <cuda_fp16.h>
#include <mma.h>
#include <cstdint>

using namespace nvcuda;

#define NNODES 100000
#define NEDGES 1600000
#define NSCANBLK 98        // ceil(NNODES/1024)

// ---------------- device scratch ----------------
__device__ int    g_deg_out[NNODES];
__device__ int    g_deg_in[NNODES];
__device__ float  g_o[NNODES];          // out_deg^{-1/2} (0 if deg==0)
__device__ float  g_i[NNODES];          // in_deg^{-1/2}  (0 if deg==0)
__device__ float  g_schain[NNODES];     // i~[r]*o[r]  (chain SpMM row scale)
__device__ float2 g_gs[NNODES];         // {1/i~[r], o~[r]/i~[r]} (GEMM epilogue scales)
__device__ int    g_rowptrA[NNODES + 1];
__device__ int    g_rowptrAT[NNODES + 1];
__device__ int    g_curA[NNODES];
__device__ int    g_curAT[NNODES];
__device__ int    g_colA[NEDGES];
__device__ int    g_colAT[NEDGES];
__device__ unsigned long long g_tstat[2][NSCANBLK];
__device__ __half g_xh [(size_t)NNODES * 64];   // i~ * x  (fp16)
__device__ __half g_y1h[(size_t)NNODES * 64];
__device__ __half g_y2h[(size_t)NNODES * 64];
__device__ __half g_y3h[(size_t)NNODES * 64];
__device__ __half g_y4h[(size_t)NNODES * 64];
__device__ __half g_Zh [(size_t)NNODES * 64];   // o~ * Z (pre-scaled for final gather)
__device__ float  g_bias[64];
__device__ __half g_Uh[128 * 320];

// ---------------- init: zero degs/status + build U/bias ----------------
__global__ void init_kernel(const float* __restrict__ Wsd, const float* __restrict__ Wds,
                            const float* __restrict__ W0sd, const float* __restrict__ W0ds,
                            const float* __restrict__ bssd, const float* __restrict__ bsds,
                            const float* __restrict__ b0sd, const float* __restrict__ b0ds) {
    int t = blockIdx.x * blockDim.x + threadIdx.x;
    if (t < NNODES) { g_deg_out[t] = 0; g_deg_in[t] = 0; }
    if (t < 2 * NSCANBLK) g_tstat[t >= NSCANBLK][t % NSCANBLK] = 0ull;

    if (t < 128 * 320) {
        int c = t / 320;
        int kk = t - c * 320;
        int b = kk >> 6;
        int k = kk & 63;
        float v;
        float coef = exp2f(-(float)b);
        if (c < 64) {
            if (b == 0) v = 0.5f * (W0sd[c * 64 + k] + W0ds[c * 64 + k]);
            else        v = coef * Wsd[(b - 1) * 4096 + c * 64 + k];
        } else {
            int cc = c - 64;
            if (b == 0)      v = 0.5f * Wds[cc * 64 + k];
            else if (b == 1) v = 0.0f;
            else             v = coef * Wds[(b - 1) * 4096 + cc * 64 + k];
        }
        g_Uh[t] = __float2half(v);
    }
    if (t < 64) {
        float bsum = b0sd[t] + b0ds[t];
        float sc = 1.0f;
        #pragma unroll
        for (int kk = 0; kk < 4; kk++) {
            bsum += sc * (bssd[kk * 64 + t] + bsds[kk * 64 + t]);
            sc *= 0.5f;
        }
        g_bias[t] = 0.5f * bsum;
    }
}

__global__ void count_deg_kernel(const int* __restrict__ ei) {
    int e = blockIdx.x * blockDim.x + threadIdx.x;
    if (e < NEDGES) {
        atomicAdd(&g_deg_out[ei[e]], 1);
        atomicAdd(&g_deg_in[ei[NEDGES + e]], 1);
    }
}

// ---------------- single-pass exclusive scan (decoupled lookback) ----------------
__global__ void scan_lookback_kernel() {
    __shared__ int s[1024];
    __shared__ int s_prefix;
    const int sel = blockIdx.y;
    const int* deg = sel ? g_deg_in : g_deg_out;
    unsigned long long* tstat = g_tstat[sel];
    int* rowptr = sel ? g_rowptrAT : g_rowptrA;
    int* cursor = sel ? g_curAT : g_curA;
    float* nrm  = sel ? g_i : g_o;

    const int tid = threadIdx.x;
    const int i = blockIdx.x * 1024 + tid;
    int v = (i < NNODES) ? deg[i] : 0;
    s[tid] = v;
    __syncthreads();
    #pragma unroll
    for (int off = 1; off < 1024; off <<= 1) {
        int t = (tid >= off) ? s[tid - off] : 0;
        __syncthreads();
        s[tid] += t;
        __syncthreads();
    }
    int incl = s[tid];
    int aggregate = s[1023];

    if (tid == 0) {
        if (blockIdx.x == 0) {
            atomicExch(&tstat[0], (2ull << 32) | (unsigned)aggregate);
            s_prefix = 0;
        } else {
            atomicExch(&tstat[blockIdx.x], (1ull << 32) | (unsigned)aggregate);
            int pfx = 0;
            int j = blockIdx.x - 1;
            for (;;) {
                unsigned long long st;
                do { st = atomicAdd(&tstat[j], 0ull); } while ((st >> 32) == 0ull);
                pfx += (int)(unsigned)st;
                if ((st >> 32) == 2ull) break;
                j--;
            }
            atomicExch(&tstat[blockIdx.x], (2ull << 32) | (unsigned)(aggregate + pfx));
            s_prefix = pfx;
        }
    }
    __syncthreads();

    if (i < NNODES) {
        int excl = s_prefix + incl - v;
        rowptr[i] = excl;
        cursor[i] = excl;
        nrm[i] = (v > 0) ? rsqrtf((float)v) : 0.0f;
    }
    if (i == 0) rowptr[NNODES] = NEDGES;
}

// ---------------- combine: derived row scales + xt = i~ * x (fp16) ----------------
__global__ void combine_kernel(const float* __restrict__ x) {
    int t = blockIdx.x * blockDim.x + threadIdx.x;
    if (t < NNODES * 16) {
        int r = t >> 4;
        float ii = g_i[r];
        float it = (ii > 0.f) ? ii : 1.0f;
        float4 v = __ldg((const float4*)x + t);
        __half2 h0 = __floats2half2_rn(it * v.x, it * v.y);
        __half2 h1 = __floats2half2_rn(it * v.z, it * v.w);
        uint2 o;
        o.x = *reinterpret_cast<unsigned*>(&h0);
        o.y = *reinterpret_cast<unsigned*>(&h1);
        *((uint2*)g_xh + t) = o;
    }
    if (t < NNODES) {
        float ii = g_i[t];
        float oo = g_o[t];
        float it = (ii > 0.f) ? ii : 1.0f;
        float ot = (oo > 0.f) ? oo : 1.0f;
        g_schain[t] = it * oo;
        g_gs[t] = make_float2(1.0f / it, ot / it);
    }
}

__global__ void fill_csr_kernel(const int* __restrict__ ei) {
    int e = blockIdx.x * blockDim.x + threadIdx.x;
    if (e < NEDGES) {
        int r = ei[e];
        int c = ei[NEDGES + e];
        int p = atomicAdd(&g_curA[r], 1);
        g_colA[p] = c;
        int q = atomicAdd(&g_curAT[c], 1);
        g_colAT[q] = r;
    }
}

// ---------------- SpMM: plain unweighted gather + per-row scale ----------------
// 8 lanes/row, 16B per lane. mode 0: yout = ss[r]*sum (fp16). mode 1: outf += bias + ss[r]*sum.
__global__ void spmm_kernel(const int* __restrict__ rowptr, const int* __restrict__ cidx,
                            const float* __restrict__ ss, const __half* __restrict__ h,
                            __half* __restrict__ yout, float* __restrict__ outf,
                            const float* __restrict__ bias, int mode) {
    int gt = blockIdx.x * blockDim.x + threadIdx.x;
    int r = gt >> 3;
    if (r >= NNODES) return;
    int lane = gt & 7;

    int k = rowptr[r];
    int end = rowptr[r + 1];
    float a[8] = {0.f, 0.f, 0.f, 0.f, 0.f, 0.f, 0.f, 0.f};
    float b[8] = {0.f, 0.f, 0.f, 0.f, 0.f, 0.f, 0.f, 0.f};

    const __half* hl = h + (lane << 3);
    while (k + 2 <= end) {
        int c0 = __ldg(cidx + k);
        int c1 = __ldg(cidx + k + 1);
        uint4 h0 = __ldg((const uint4*)(hl + ((size_t)c0 << 6)));
        uint4 h1 = __ldg((const uint4*)(hl + ((size_t)c1 << 6)));
        const unsigned* p0 = &h0.x;
        const unsigned* p1 = &h1.x;
        #pragma unroll
        for (int q = 0; q < 4; q++) {
            float2 f0 = __half22float2(*reinterpret_cast<const __half2*>(p0 + q));
            float2 f1 = __half22float2(*reinterpret_cast<const __half2*>(p1 + q));
            a[q * 2]     += f0.x;
            a[q * 2 + 1] += f0.y;
            b[q * 2]     += f1.x;
            b[q * 2 + 1] += f1.y;
        }
        k += 2;
    }
    if (k < end) {
        int c0 = __ldg(cidx + k);
        uint4 h0 = __ldg((const uint4*)(hl + ((size_t)c0 << 6)));
        const unsigned* p0 = &h0.x;
        #pragma unroll
        for (int q = 0; q < 4; q++) {
            float2 f0 = __half22float2(*reinterpret_cast<const __half2*>(p0 + q));
            a[q * 2]     += f0.x;
            a[q * 2 + 1] += f0.y;
        }
    }
    #pragma unroll
    for (int q = 0; q < 8; q++) a[q] += b[q];

    float s = ss[r];
    if (mode == 0) {
        uint4 o;
        __half2 h0 = __floats2half2_rn(s * a[0], s * a[1]);
        __half2 h1 = __floats2half2_rn(s * a[2], s * a[3]);
        __half2 h2 = __floats2half2_rn(s * a[4], s * a[5]);
        __half2 h3 = __floats2half2_rn(s * a[6], s * a[7]);
        o.x = *reinterpret_cast<unsigned*>(&h0);
        o.y = *reinterpret_cast<unsigned*>(&h1);
        o.z = *reinterpret_cast<unsigned*>(&h2);
        o.w = *reinterpret_cast<unsigned*>(&h3);
        *(uint4*)(yout + ((size_t)r << 6) + (lane << 3)) = o;
    } else {
        size_t off = ((size_t)r << 6) + (lane << 3);
        float4 p0 = *reinterpret_cast<float4*>(outf + off);
        float4 p1 = *reinterpret_cast<float4*>(outf + off + 4);
        float4 bv0 = *reinterpret_cast<const float4*>(bias + (lane << 3));
        float4 bv1 = *reinterpret_cast<const float4*>(bias + (lane << 3) + 4);
        float4 r0, r1;
        r0.x = p0.x + bv0.x + s * a[0];
        r0.y = p0.y + bv0.y + s * a[1];
        r0.z = p0.z + bv0.z + s * a[2];
        r0.w = p0.w + bv0.w + s * a[3];
        r1.x = p1.x + bv1.x + s * a[4];
        r1.y = p1.y + bv1.y + s * a[5];
        r1.z = p1.z + bv1.z + s * a[6];
        r1.w = p1.w + bv1.w + s * a[7];
        *reinterpret_cast<float4*>(outf + off)     = r0;
        *reinterpret_cast<float4*>(outf + off + 4) = r1;
    }
}

// ---------------- Mega-GEMM via HMMA with per-row epilogue scales ----------------
#define LDS_K 40
__global__ __launch_bounds__(256) void mega_gemm_kernel(
    const __half* __restrict__ xh,
    float* __restrict__ out, __half* __restrict__ Zh)
{
    __shared__ __half sA[128 * LDS_K];
    __shared__ __half sB[128 * LDS_K];
    __shared__ float patch[8][16 * 16];

    const int tid  = threadIdx.x;
    const int wid  = tid >> 5;
    const int row0 = blockIdx.x * 128;
    const int wr   = wid & 3;
    const int wc   = wid >> 2;

    wmma::fragment<wmma::accumulator, 16, 16, 16, float> acc[2][4];
    #pragma unroll
    for (int i = 0; i < 2; i++)
        #pragma unroll
        for (int j = 0; j < 4; j++) wmma::fill_fragment(acc[i][j], 0.0f);

    const __half* srcs[5] = {xh, g_y1h, g_y2h, g_y3h, g_y4h};

    const int srow  = tid >> 1;
    const int spart = (tid & 1) * 16;

    #pragma unroll
    for (int g = 0; g < 10; g++) {
        const __half* src = srcs[g >> 1];
        const int kbase = (g & 1) * 32;

        __syncthreads();
        {
            int grow = row0 + srow;
            uint4 v0 = make_uint4(0, 0, 0, 0), v1 = v0;
            if (grow < NNODES) {
                const uint4* p = (const uint4*)(src + (size_t)grow * 64 + kbase + spart);
                v0 = __ldg(p);
                v1 = __ldg(p + 1);
            }
            *(uint4*)&sA[srow * LDS_K + spart]     = v0;
            *(uint4*)&sA[srow * LDS_K + spart + 8] = v1;
        }
        {
            const uint4* p = (const uint4*)(g_Uh + (size_t)srow * 320 + (g >> 1) * 64 + kbase + spart);
            uint4 v0 = __ldg(p);
            uint4 v1 = __ldg(p + 1);
            *(uint4*)&sB[srow * LDS_K + spart]     = v0;
            *(uint4*)&sB[srow * LDS_K + spart + 8] = v1;
        }
        __syncthreads();

        #pragma unroll
        for (int ks = 0; ks < 32; ks += 16) {
            wmma::fragment<wmma::matrix_a, 16, 16, 16, __half, wmma::row_major> af[2];
            wmma::load_matrix_sync(af[0], &sA[(wr * 32 +  0) * LDS_K + ks], LDS_K);
            wmma::load_matrix_sync(af[1], &sA[(wr * 32 + 16) * LDS_K + ks], LDS_K);
            #pragma unroll
            for (int j = 0; j < 4; j++) {
                wmma::fragment<wmma::matrix_b, 16, 16, 16, __half, wmma::col_major> bf;
                wmma::load_matrix_sync(bf, &sB[(wc * 64 + j * 16) * LDS_K + ks], LDS_K);
                wmma::mma_sync(acc[0][j], af[0], bf, acc[0][j]);
                wmma::mma_sync(acc[1][j], af[1], bf, acc[1][j]);
            }
        }
    }

    const int lane = tid & 31;
    #pragma unroll
    for (int i = 0; i < 2; i++) {
        int rbase = row0 + wr * 32 + i * 16;
        if (rbase >= NNODES) continue;
        #pragma unroll
        for (int j = 0; j < 4; j++) {
            wmma::store_matrix_sync(patch[wid], acc[i][j], 16, wmma::mem_row_major);
            __syncwarp();
            int pr = lane >> 1;
            int pc = (lane & 1) * 8;
            int r = rbase + pr;
            const float* pp = &patch[wid][pr * 16 + pc];
            float2 gsr = g_gs[r];
            if (wc == 0) {
                float s = gsr.x;   // 1/i~
                float4 o0 = make_float4(pp[0] * s, pp[1] * s, pp[2] * s, pp[3] * s);
                float4 o1 = make_float4(pp[4] * s, pp[5] * s, pp[6] * s, pp[7] * s);
                float* dst = out + (size_t)r * 64 + j * 16 + pc;
                *reinterpret_cast<float4*>(dst)     = o0;
                *reinterpret_cast<float4*>(dst + 4) = o1;
            } else {
                float s = gsr.y;   // o~/i~
                __half2 h0 = __floats2half2_rn(pp[0] * s, pp[1] * s);
                __half2 h1 = __floats2half2_rn(pp[2] * s, pp[3] * s);
                __half2 h2 = __floats2half2_rn(pp[4] * s, pp[5] * s);
                __half2 h3 = __floats2half2_rn(pp[6] * s, pp[7] * s);
                uint4 o;
                o.x = *reinterpret_cast<unsigned*>(&h0);
                o.y = *reinterpret_cast<unsigned*>(&h1);
                o.z = *reinterpret_cast<unsigned*>(&h2);
                o.w = *reinterpret_cast<unsigned*>(&h3);
                *(uint4*)(Zh + (size_t)r * 64 + j * 16 + pc) = o;
            }
            __syncwarp();
        }
    }
}

// ---------------- launch ----------------
extern "C" void kernel_launch(void* const* d_in, const int* in_sizes, int n_in,
                              void* d_out, int out_size) {
    const float* x    = (const float*)d_in[0];
    const int*   ei   = (const int*)d_in[1];
    const float* Wsd  = (const float*)d_in[2];
    const float* bssd = (const float*)d_in[3];
    const float* Wds  = (const float*)d_in[4];
    const float* bsds = (const float*)d_in[5];
    const float* W0sd = (const float*)d_in[6];
    const float* b0sd = (const float*)d_in[7];
    const float* W0ds = (const float*)d_in[8];
    const float* b0ds = (const float*)d_in[9];
    float* out = (float*)d_out;

    void* tmp;
    cudaGetSymbolAddress(&tmp, g_xh);       __half* xh  = (__half*)tmp;
    cudaGetSymbolAddress(&tmp, g_y1h);      __half* y1h = (__half*)tmp;
    cudaGetSymbolAddress(&tmp, g_y2h);      __half* y2h = (__half*)tmp;
    cudaGetSymbolAddress(&tmp, g_y3h);      __half* y3h = (__half*)tmp;
    cudaGetSymbolAddress(&tmp, g_y4h);      __half* y4h = (__half*)tmp;
    cudaGetSymbolAddress(&tmp, g_Zh);       __half* Zh  = (__half*)tmp;
    cudaGetSymbolAddress(&tmp, g_bias);     float* bias = (float*)tmp;
    cudaGetSymbolAddress(&tmp, g_rowptrA);  int* rpA  = (int*)tmp;
    cudaGetSymbolAddress(&tmp, g_rowptrAT); int* rpAT = (int*)tmp;
    cudaGetSymbolAddress(&tmp, g_colA);     int* cA   = (int*)tmp;
    cudaGetSymbolAddress(&tmp, g_colAT);    int* cAT  = (int*)tmp;
    cudaGetSymbolAddress(&tmp, g_schain);   float* schain = (float*)tmp;
    cudaGetSymbolAddress(&tmp, g_i);        float* ni = (float*)tmp;

    const int nblk_nodes = (NNODES + 255) / 256;         // 391
    const int nblk_edges = (NEDGES + 255) / 256;         // 6250
    const int nblk_comb  = (NNODES * 16 + 255) / 256;    // 6250
    const int nblk_spmm  = (NNODES * 8 + 255) / 256;     // 3125
    const int nblk_gemm  = (NNODES + 127) / 128;         // 782

    // ---- preprocessing ----
    init_kernel<<<nblk_nodes, 256>>>(Wsd, Wds, W0sd, W0ds, bssd, bsds, b0sd, b0ds);
    count_deg_kernel<<<nblk_edges, 256>>>(ei);
    scan_lookback_kernel<<<dim3(NSCANBLK, 2), 1024>>>();
    combine_kernel<<<nblk_comb, 256>>>(x);
    fill_csr_kernel<<<nblk_edges, 256>>>(ei);

    // ---- hop chain: t_k = (i~ o)[r] * plain-gather(t_{k-1}) ----
    spmm_kernel<<<nblk_spmm, 256>>>(rpA, cA, schain, xh,  y1h, nullptr, nullptr, 0);
    spmm_kernel<<<nblk_spmm, 256>>>(rpA, cA, schain, y1h, y2h, nullptr, nullptr, 0);
    spmm_kernel<<<nblk_spmm, 256>>>(rpA, cA, schain, y2h, y3h, nullptr, nullptr, 0);
    spmm_kernel<<<nblk_spmm, 256>>>(rpA, cA, schain, y3h, y4h, nullptr, nullptr, 0);

    // ---- fused HMMA GEMM with per-row rescale: out, Zhat ----
    mega_gemm_kernel<<<nblk_gemm, 256>>>(xh, out, Zh);

    // ---- out += bias + i[r] * plain-gather(Zhat) ----
    spmm_kernel<<<nblk_spmm, 256>>>(rpAT, cAT, ni, Zh, nullptr, out, bias, 1);
}